// round 2
// baseline (speedup 1.0000x reference)
#include <cuda_runtime.h>
#include <math.h>

// Problem constants
#define Bq   8
#define Nn   8192
#define Hh   256
#define Ff   320
#define Ss   32
#define Mtot (Bq * Nn)      // 65536
#define NSPLIT 16

// Scratch (static device globals — no cudaMalloc allowed)
__device__ float g_xall[(size_t)Mtot * Hh];        // gated features [B*N, H] (67 MB)
__device__ float g_norm[Mtot];                     // per-node L2 norm
__device__ float g_part[NSPLIT * Bq * Ss * Hh];    // split-K partials for pooling

// ---- packed f32x2 helpers (FFMA2: 2x fp32 fma throughput on sm_103a) ----
__device__ __forceinline__ unsigned long long pk2(float lo, float hi) {
    unsigned long long r;
    asm("mov.b64 %0, {%1, %2};" : "=l"(r) : "f"(lo), "f"(hi));
    return r;
}
__device__ __forceinline__ unsigned long long fma2(unsigned long long a,
                                                   unsigned long long b,
                                                   unsigned long long c) {
    unsigned long long d;
    asm("fma.rn.f32x2 %0, %1, %2, %3;" : "=l"(d) : "l"(a), "l"(b), "l"(c));
    return d;
}
__device__ __forceinline__ float2 upk2(unsigned long long v) {
    float lo, hi;
    asm("mov.b64 {%0, %1}, %2;" : "=f"(lo), "=f"(hi) : "l"(v));
    return make_float2(lo, hi);
}

__device__ __forceinline__ float gate_fn(float zi, float zj) {
    float s = 1.0f / (1.0f + expf(-zi));
    return s * tanhf(zj);
}

// ============================================================================
// Kernel A: fused dual GEMM + sigmoid*tanh gating.
//   Ci[m,h] = sum_f x[m,f]*Wi[h,f] + bi[h];  Cj likewise
//   g_xall[m,h] = sigmoid(Ci)*tanh(Cj)
// Block tile: 64 m x 64 h, BK=16. 256 threads, each 4m x 4h for BOTH GEMMs.
// ============================================================================
__global__ __launch_bounds__(256, 2) void k_gemm_gate(
    const float* __restrict__ x,
    const float* __restrict__ Wi, const float* __restrict__ bi,
    const float* __restrict__ Wj, const float* __restrict__ bj)
{
    __shared__ float As [16][64];
    __shared__ float Bis[16][64];
    __shared__ float Bjs[16][64];

    const int m0 = blockIdx.x * 64;
    const int h0 = blockIdx.y * 64;
    const int t  = threadIdx.x;
    const int lr = t >> 2;            // 0..63 load row
    const int lc = (t & 3) * 4;       // k offset (float4)
    const int mf = (t >> 4) * 4;      // thread m-frag
    const int hf = (t & 15) * 4;      // thread h-frag

    const float* xg  = x  + (size_t)(m0 + lr) * Ff + lc;
    const float* wig = Wi + (size_t)(h0 + lr) * Ff + lc;
    const float* wjg = Wj + (size_t)(h0 + lr) * Ff + lc;

    unsigned long long ci[4][2], cj[4][2];
    const unsigned long long zz = pk2(0.0f, 0.0f);
#pragma unroll
    for (int i = 0; i < 4; i++) {
        ci[i][0] = zz; ci[i][1] = zz;
        cj[i][0] = zz; cj[i][1] = zz;
    }

    for (int k0 = 0; k0 < Ff; k0 += 16) {
        float4 av = *(const float4*)(xg  + k0);
        float4 bv = *(const float4*)(wig + k0);
        float4 cv = *(const float4*)(wjg + k0);
        __syncthreads();
        As [lc + 0][lr] = av.x; As [lc + 1][lr] = av.y;
        As [lc + 2][lr] = av.z; As [lc + 3][lr] = av.w;
        Bis[lc + 0][lr] = bv.x; Bis[lc + 1][lr] = bv.y;
        Bis[lc + 2][lr] = bv.z; Bis[lc + 3][lr] = bv.w;
        Bjs[lc + 0][lr] = cv.x; Bjs[lc + 1][lr] = cv.y;
        Bjs[lc + 2][lr] = cv.z; Bjs[lc + 3][lr] = cv.w;
        __syncthreads();
#pragma unroll
        for (int kk = 0; kk < 16; kk++) {
            float4 a = *(const float4*)&As[kk][mf];
            ulonglong2 b2 = *(const ulonglong2*)&Bis[kk][hf];
            ulonglong2 c2 = *(const ulonglong2*)&Bjs[kk][hf];
            unsigned long long ap[4];
            ap[0] = pk2(a.x, a.x); ap[1] = pk2(a.y, a.y);
            ap[2] = pk2(a.z, a.z); ap[3] = pk2(a.w, a.w);
#pragma unroll
            for (int i = 0; i < 4; i++) {
                ci[i][0] = fma2(ap[i], b2.x, ci[i][0]);
                ci[i][1] = fma2(ap[i], b2.y, ci[i][1]);
                cj[i][0] = fma2(ap[i], c2.x, cj[i][0]);
                cj[i][1] = fma2(ap[i], c2.y, cj[i][1]);
            }
        }
    }

    float4 bi4 = *(const float4*)&bi[h0 + hf];
    float4 bj4 = *(const float4*)&bj[h0 + hf];
#pragma unroll
    for (int i = 0; i < 4; i++) {
        float2 zi0 = upk2(ci[i][0]), zi1 = upk2(ci[i][1]);
        float2 zj0 = upk2(cj[i][0]), zj1 = upk2(cj[i][1]);
        float4 o;
        o.x = gate_fn(zi0.x + bi4.x, zj0.x + bj4.x);
        o.y = gate_fn(zi0.y + bi4.y, zj0.y + bj4.y);
        o.z = gate_fn(zi1.x + bi4.z, zj1.x + bj4.z);
        o.w = gate_fn(zi1.y + bi4.w, zj1.y + bj4.w);
        *(float4*)&g_xall[(size_t)(m0 + mf + i) * Hh + h0 + hf] = o;
    }
}

// ============================================================================
// Kernel B: per-node L2 norm over H=256. One warp per node.
// ============================================================================
__global__ __launch_bounds__(256) void k_norm() {
    int node = (blockIdx.x * blockDim.x + threadIdx.x) >> 5;
    int lane = threadIdx.x & 31;
    const float4* row = (const float4*)&g_xall[(size_t)node * Hh];
    float4 v0 = row[lane];
    float4 v1 = row[lane + 32];
    float s = v0.x * v0.x + v0.y * v0.y + v0.z * v0.z + v0.w * v0.w
            + v1.x * v1.x + v1.y * v1.y + v1.z * v1.z + v1.w * v1.w;
#pragma unroll
    for (int o = 16; o > 0; o >>= 1) s += __shfl_xor_sync(0xFFFFFFFFu, s, o);
    if (lane == 0) g_norm[node] = sqrtf(s);
}

// ============================================================================
// Kernel C: masked softmax over nodes. One block per (b,s) row of 8192.
//   e = (t>0) ? exp(t) : 0 ; w = (sum>0) ? e/sum : 0
// ============================================================================
__global__ __launch_bounds__(256) void k_weight(const float* __restrict__ node_map,
                                                float* __restrict__ wout) {
    __shared__ float e[Nn];       // 32 KB
    __shared__ float red[256];
    int bs = blockIdx.x;          // b*32 + s
    int b  = bs >> 5;
    const float* nm  = node_map + (size_t)bs * Nn;
    const float* nrm = g_norm + (size_t)b * Nn;
    int t = threadIdx.x;
    float part = 0.0f;
    for (int n = t; n < Nn; n += 256) {
        float v  = nm[n] * nrm[n];
        float ev = (v > 0.0f) ? expf(v) : 0.0f;
        e[n] = ev;
        part += ev;
    }
    red[t] = part;
    __syncthreads();
#pragma unroll
    for (int o = 128; o > 0; o >>= 1) {
        if (t < o) red[t] += red[t + o];
        __syncthreads();
    }
    float sum = red[0];
    float inv = (sum > 0.0f) ? (1.0f / sum) : 0.0f;
    float* wrow = wout + (size_t)bs * Nn;
    for (int n = t; n < Nn; n += 256) wrow[n] = e[n] * inv;
}

// ============================================================================
// Kernel D: split-K pooled GEMM partials.
//   part[c,b,s,h] = sum_{n in chunk c} w[b,s,n] * xall[b,n,h]
// Grid (NSPLIT, H/128, B); block 256, thread tile 4s x 4h.
// ============================================================================
__global__ __launch_bounds__(256) void k_pool(const float* __restrict__ w) {
    __shared__ float xs[32][128];   // 16 KB
    __shared__ float ws[32][32];    //  4 KB, [n][s]
    int chunk = blockIdx.x;
    int h0    = blockIdx.y * 128;
    int b     = blockIdx.z;
    int t     = threadIdx.x;
    int hq = (t & 31) * 4;          // h frag
    int sq = (t >> 5) * 4;          // s frag
    float acc[4][4] = {};
    int nbase = chunk * (Nn / NSPLIT);   // 512-node chunk

    for (int n0 = 0; n0 < Nn / NSPLIT; n0 += 32) {
        __syncthreads();
#pragma unroll
        for (int i = 0; i < 4; i++) {
            int idx = t + i * 256;          // 0..1023
            int nn  = idx >> 5;             // 0..31
            int hh  = (idx & 31) * 4;       // 0..124
            *(float4*)&xs[nn][hh] =
                *(const float4*)&g_xall[(size_t)(b * Nn + nbase + n0 + nn) * Hh + h0 + hh];
        }
        {
            int s  = t >> 3;                // 0..31
            int nn = (t & 7) * 4;           // 0..28
            float4 wv = *(const float4*)&w[(size_t)(b * Ss + s) * Nn + nbase + n0 + nn];
            ws[nn + 0][s] = wv.x; ws[nn + 1][s] = wv.y;
            ws[nn + 2][s] = wv.z; ws[nn + 3][s] = wv.w;
        }
        __syncthreads();
#pragma unroll
        for (int nc = 0; nc < 32; nc++) {
            float4 a  = *(const float4*)&xs[nc][hq];
            float4 wv = *(const float4*)&ws[nc][sq];
            acc[0][0] += wv.x * a.x; acc[0][1] += wv.x * a.y; acc[0][2] += wv.x * a.z; acc[0][3] += wv.x * a.w;
            acc[1][0] += wv.y * a.x; acc[1][1] += wv.y * a.y; acc[1][2] += wv.y * a.z; acc[1][3] += wv.y * a.w;
            acc[2][0] += wv.z * a.x; acc[2][1] += wv.z * a.y; acc[2][2] += wv.z * a.z; acc[2][3] += wv.z * a.w;
            acc[3][0] += wv.w * a.x; acc[3][1] += wv.w * a.y; acc[3][2] += wv.w * a.z; acc[3][3] += wv.w * a.w;
        }
    }
#pragma unroll
    for (int i = 0; i < 4; i++) {
        float4 o = make_float4(acc[i][0], acc[i][1], acc[i][2], acc[i][3]);
        *(float4*)&g_part[(size_t)((chunk * Bq + b) * Ss + sq + i) * Hh + h0 + hq] = o;
    }
}

// ============================================================================
// Kernel E: deterministic split-K reduce + tanh
// ============================================================================
__global__ __launch_bounds__(256) void k_final(float* __restrict__ out) {
    int g = blockIdx.x * blockDim.x + threadIdx.x;   // 0..65535
    float s = 0.0f;
#pragma unroll
    for (int c = 0; c < NSPLIT; c++) s += g_part[(size_t)c * (Bq * Ss * Hh) + g];
    out[g] = tanhf(s);
}

// ============================================================================
extern "C" void kernel_launch(void* const* d_in, const int* in_sizes, int n_in,
                              void* d_out, int out_size) {
    const float* x        = (const float*)d_in[0];
    const float* node_map = (const float*)d_in[1];
    const float* Wi       = (const float*)d_in[2];
    const float* bi       = (const float*)d_in[3];
    const float* Wj       = (const float*)d_in[4];
    const float* bj       = (const float*)d_in[5];
    float* out  = (float*)d_out;
    float* wout = out + (size_t)Bq * Ss * Hh;   // weight output region (65536..)

    k_gemm_gate<<<dim3(Mtot / 64, Hh / 64), 256>>>(x, Wi, bi, Wj, bj);
    k_norm<<<(Mtot * 32) / 256, 256>>>();
    k_weight<<<Bq * Ss, 256>>>(node_map, wout);
    k_pool<<<dim3(NSPLIT, Hh / 128, Bq), 256>>>(wout);
    k_final<<<(Bq * Ss * Hh) / 256, 256>>>(out);
}

// round 9
// speedup vs baseline: 2.3522x; 2.3522x over previous
#include <cuda_runtime.h>
#include <cuda_bf16.h>
#include <math.h>
#include <stdint.h>

// Problem constants
#define Bq   8
#define Nn   8192
#define Hh   256
#define Ff   320
#define Ss   32
#define Mtot (Bq * Nn)      // 65536
#define NSPLIT 32

// Scratch (static device globals — no cudaMalloc allowed)
__device__ float g_xall[(size_t)Mtot * Hh];        // gated features [B*N, H]
__device__ float g_norm[Mtot];                     // per-node L2 norm
__device__ float g_part[NSPLIT * Bq * Ss * Hh];    // split-K partials
// combined weights [Wi;Wj] = 512 rows x 320 cols, bf16 hi/lo,
// tiled as [kchunk 10][n 512][k 32] for direct cp.async
__device__ __nv_bfloat16 g_wh[512 * Ff];
__device__ __nv_bfloat16 g_wl[512 * Ff];

// ======================= helpers ============================================
__device__ __forceinline__ uint32_t smem_u32(const void* p) {
    uint32_t a;
    asm("{ .reg .u64 t; cvta.to.shared.u64 t, %1; cvt.u32.u64 %0, t; }"
        : "=r"(a) : "l"(p));
    return a;
}
// SW64 swizzle for 64B rows: bits[5:4] ^= bits[8:7]
__device__ __forceinline__ uint32_t swz(uint32_t o) {
    return o ^ ((o >> 3) & 0x30);
}
__device__ __forceinline__ void cp16(uint32_t dst, const void* src) {
    asm volatile("cp.async.cg.shared.global [%0], [%1], 16;"
                 :: "r"(dst), "l"(src) : "memory");
}
#define CP_COMMIT() asm volatile("cp.async.commit_group;" ::: "memory")
#define CP_WAIT0()  asm volatile("cp.async.wait_group 0;" ::: "memory")

#define LDSM4(r, addr)                                                         \
    asm volatile("ldmatrix.sync.aligned.m8n8.x4.shared.b16 {%0,%1,%2,%3}, [%4];" \
                 : "=r"((r)[0]), "=r"((r)[1]), "=r"((r)[2]), "=r"((r)[3])      \
                 : "r"(addr))

__device__ __forceinline__ void mma16816(float* d, const uint32_t* a,
                                         uint32_t b0, uint32_t b1) {
    asm volatile(
        "mma.sync.aligned.m16n8k16.row.col.f32.bf16.bf16.f32 "
        "{%0,%1,%2,%3}, {%4,%5,%6,%7}, {%8,%9}, {%0,%1,%2,%3};"
        : "+f"(d[0]), "+f"(d[1]), "+f"(d[2]), "+f"(d[3])
        : "r"(a[0]), "r"(a[1]), "r"(a[2]), "r"(a[3]), "r"(b0), "r"(b1));
}

__device__ __forceinline__ float gate_fn(float zi, float zj) {
    float s = 1.0f / (1.0f + expf(-zi));
    return s * tanhf(zj);
}

// SMEM map (dynamic, bytes):
//  [0      , 16384 )  A stages: s*8192 + {hi:0, lo:4096}, 64 rows x 64B
//  [16384  , 147456)  B stages: 16384 + s*65536 + {hi:0, lo:32768}, 512 rows x 64B
//  [147456 , 149504)  bias 512 f32
//  epilogue reuses [0,131072) as fp32 exchange [64][512]
#define SM_B    16384
#define SM_BIAS 147456
#define SM_TOT  149504

// ============================================================================
// k_wconv: split+tile weights: g_wh/g_wl[(c*512+n)*32+kk], f = c*32+kk
// ============================================================================
__global__ __launch_bounds__(256) void k_wconv(const float* __restrict__ Wi,
                                               const float* __restrict__ Wj) {
    int i = blockIdx.x * 256 + threadIdx.x;   // 0..163839
    int c  = i >> 14;            // /16384
    int r  = i & 16383;
    int n  = r >> 5;
    int kk = r & 31;
    int f  = c * 32 + kk;
    float v = (n < 256) ? Wi[n * Ff + f] : Wj[(n - 256) * Ff + f];
    __nv_bfloat16 h = __float2bfloat16(v);
    g_wh[i] = h;
    g_wl[i] = __float2bfloat16(v - __bfloat162float(h));
}

// ============================================================================
// k_gemm_mma: dual GEMM (bf16 split-2, 3 HMMA passes) + gate + fused L2 norm.
// CTA: 64 M-rows x 512 N-cols (Di = n<256, Dj = n>=256). 512 thr = 16 warps.
// Warp (wm=wid/4, wn=wid%4): tile 16m x 128n.
// ============================================================================
__global__ __launch_bounds__(512, 1) void k_gemm_mma(
    const float* __restrict__ x,
    const float* __restrict__ bi, const float* __restrict__ bj)
{
    extern __shared__ __align__(128) char smem[];
    const uint32_t sb = smem_u32(smem);
    const int t    = threadIdx.x;
    const int lane = t & 31;
    const int wid  = t >> 5;
    const int wm   = wid >> 2;
    const int wn   = wid & 3;
    const int m0   = blockIdx.x * 64;

    // bias preload (512 threads exactly)
    float* biasS = (float*)(smem + SM_BIAS);
    biasS[t] = (t < 256) ? bi[t] : bj[t - 256];

    float acc[16][4] = {};

    // ---- x prefetch addressing: thread owns (row = t/8, 4 floats at col (t%8)*4)
    const int xrow = t >> 3, xc = t & 7;
    const float* xptr = x + (size_t)(m0 + xrow) * Ff + xc * 4;

    // ---- B issue: 2048 16B-chunks per (hi|lo) per stage; 4 per thread each
    auto issueB = [&](int it, int buf) {
        uint32_t base = sb + SM_B + buf * 65536;
#pragma unroll
        for (int i = 0; i < 4; i++) {
            int e  = t + i * 512;          // 0..2047
            int n  = e >> 2;
            int kc = e & 3;
            uint32_t so = swz((uint32_t)n * 64 + kc * 16);
            size_t s = (size_t)it * 16384 + (size_t)n * 32 + kc * 8;
            cp16(base + so,         g_wh + s);
            cp16(base + 32768 + so, g_wl + s);
        }
        CP_COMMIT();
    };
    // ---- A convert fp32 -> bf16 hi/lo, STS swizzled
    auto stsA = [&](float4 v, int buf) {
        __nv_bfloat16 h0 = __float2bfloat16(v.x), h1 = __float2bfloat16(v.y);
        __nv_bfloat16 h2 = __float2bfloat16(v.z), h3 = __float2bfloat16(v.w);
        __nv_bfloat16 l0 = __float2bfloat16(v.x - __bfloat162float(h0));
        __nv_bfloat16 l1 = __float2bfloat16(v.y - __bfloat162float(h1));
        __nv_bfloat16 l2 = __float2bfloat16(v.z - __bfloat162float(h2));
        __nv_bfloat16 l3 = __float2bfloat16(v.w - __bfloat162float(h3));
        uint2 ph, pl;
        ph.x = (uint32_t)__bfloat16_as_ushort(h0) | ((uint32_t)__bfloat16_as_ushort(h1) << 16);
        ph.y = (uint32_t)__bfloat16_as_ushort(h2) | ((uint32_t)__bfloat16_as_ushort(h3) << 16);
        pl.x = (uint32_t)__bfloat16_as_ushort(l0) | ((uint32_t)__bfloat16_as_ushort(l1) << 16);
        pl.y = (uint32_t)__bfloat16_as_ushort(l2) | ((uint32_t)__bfloat16_as_ushort(l3) << 16);
        uint32_t off = swz((uint32_t)xrow * 64 + xc * 8);
        *(uint2*)(smem + buf * 8192 + off)        = ph;
        *(uint2*)(smem + buf * 8192 + 4096 + off) = pl;
    };
    // ---- compute one k32 stage
    auto compute = [&](int buf) {
        uint32_t aBase = sb + buf * 8192;
        uint32_t bBase = sb + SM_B + buf * 65536;
        const uint32_t arow = wm * 16 + (lane & 7) + ((lane >> 3) & 1) * 8;
        const uint32_t c16  = (lane >> 4) & 1;
        const uint32_t brow = wn * 128 + (lane & 7) + ((lane >> 3) & 1) * 8;
#pragma unroll
        for (int k16 = 0; k16 < 2; k16++) {
            uint32_t ao = swz(arow * 64 + k16 * 32 + c16 * 16);
            uint32_t ah[4], al[4];
            LDSM4(ah, aBase + ao);
            LDSM4(al, aBase + 4096 + ao);
#pragma unroll
            for (int bn = 0; bn < 8; bn++) {
                uint32_t bo = swz((brow + bn * 16) * 64 + k16 * 32 + c16 * 16);
                uint32_t bh[4], bl[4];
                LDSM4(bh, bBase + bo);
                LDSM4(bl, bBase + 32768 + bo);
                mma16816(acc[bn * 2],     ah, bh[0], bh[2]);
                mma16816(acc[bn * 2 + 1], ah, bh[1], bh[3]);
                mma16816(acc[bn * 2],     ah, bl[0], bl[2]);
                mma16816(acc[bn * 2 + 1], ah, bl[1], bl[3]);
                mma16816(acc[bn * 2],     al, bh[0], bh[2]);
                mma16816(acc[bn * 2 + 1], al, bh[1], bh[3]);
            }
        }
    };

    // ---- prologue
    float4 xv = *(const float4*)xptr;     // chunk 0
    issueB(0, 0);
    stsA(xv, 0);

    // ---- main loop: 10 k32 chunks, double buffered
    for (int it = 0; it < 10; it++) {
        int buf = it & 1;
        CP_WAIT0();
        __syncthreads();     // A(it) visible; compute(it-1) done -> buf^1 free
        float4 xn;
        if (it < 9) {
            xn = *(const float4*)(xptr + (it + 1) * 32);
            issueB(it + 1, buf ^ 1);
        }
        compute(buf);
        if (it < 9) stsA(xn, buf ^ 1);
    }
    __syncthreads();

    // ---- epilogue: exchange acc via smem fp32 [64][512]
    float* ex = (float*)smem;
#pragma unroll
    for (int fn = 0; fn < 16; fn++) {
        int col = wn * 128 + fn * 8 + (lane & 3) * 2;
        int row = wm * 16 + (lane >> 2);
        ex[row * 512 + col]           = acc[fn][0];
        ex[row * 512 + col + 1]       = acc[fn][1];
        ex[(row + 8) * 512 + col]     = acc[fn][2];
        ex[(row + 8) * 512 + col + 1] = acc[fn][3];
    }
    __syncthreads();

    // gate + write g_xall + fused norm. thread: row = t/8, h = (t%8)*4 + j*32
    const int grow = t >> 3, gc = t & 7;
    float nrm = 0.0f;
#pragma unroll
    for (int j = 0; j < 8; j++) {
        int h = gc * 4 + j * 32;
        float4 di = *(float4*)&ex[grow * 512 + h];
        float4 dj = *(float4*)&ex[grow * 512 + 256 + h];
        float4 bi4 = *(float4*)&biasS[h];
        float4 bj4 = *(float4*)&biasS[256 + h];
        float4 o;
        o.x = gate_fn(di.x + bi4.x, dj.x + bj4.x);
        o.y = gate_fn(di.y + bi4.y, dj.y + bj4.y);
        o.z = gate_fn(di.z + bi4.z, dj.z + bj4.z);
        o.w = gate_fn(di.w + bi4.w, dj.w + bj4.w);
        nrm += o.x * o.x + o.y * o.y + o.z * o.z + o.w * o.w;
        *(float4*)&g_xall[(size_t)(m0 + grow) * Hh + h] = o;
    }
#pragma unroll
    for (int o = 4; o > 0; o >>= 1) nrm += __shfl_xor_sync(0xFFFFFFFFu, nrm, o);
    if ((lane & 7) == 0) g_norm[m0 + grow] = sqrtf(nrm);
}

// ============================================================================
// k_weight: masked softmax over nodes. One block per (b,s).
// ============================================================================
__global__ __launch_bounds__(256) void k_weight(const float* __restrict__ node_map,
                                                float* __restrict__ wout) {
    __shared__ float e[Nn];
    __shared__ float red[256];
    int bs = blockIdx.x;
    int b  = bs >> 5;
    const float* nm  = node_map + (size_t)bs * Nn;
    const float* nrm = g_norm + (size_t)b * Nn;
    int t = threadIdx.x;
    float part = 0.0f;
    for (int n = t; n < Nn; n += 256) {
        float v  = nm[n] * nrm[n];
        float ev = (v > 0.0f) ? expf(v) : 0.0f;
        e[n] = ev;
        part += ev;
    }
    red[t] = part;
    __syncthreads();
#pragma unroll
    for (int o = 128; o > 0; o >>= 1) {
        if (t < o) red[t] += red[t + o];
        __syncthreads();
    }
    float sum = red[0];
    float inv = (sum > 0.0f) ? (1.0f / sum) : 0.0f;
    float* wrow = wout + (size_t)bs * Nn;
    for (int n = t; n < Nn; n += 256) wrow[n] = e[n] * inv;
}

// ============================================================================
// k_pool: split-K pooled GEMM partials. NSPLIT=32 -> 512 CTAs.
// ============================================================================
__global__ __launch_bounds__(256) void k_pool(const float* __restrict__ w) {
    __shared__ float xs[32][128];
    __shared__ float ws[32][32];
    int chunk = blockIdx.x;
    int h0    = blockIdx.y * 128;
    int b     = blockIdx.z;
    int t     = threadIdx.x;
    int hq = (t & 31) * 4;
    int sq = (t >> 5) * 4;
    float acc[4][4] = {};
    int nbase = chunk * (Nn / NSPLIT);

    for (int n0 = 0; n0 < Nn / NSPLIT; n0 += 32) {
        __syncthreads();
#pragma unroll
        for (int i = 0; i < 4; i++) {
            int idx = t + i * 256;
            int nn  = idx >> 5;
            int hh  = (idx & 31) * 4;
            *(float4*)&xs[nn][hh] =
                *(const float4*)&g_xall[(size_t)(b * Nn + nbase + n0 + nn) * Hh + h0 + hh];
        }
        {
            int s  = t >> 3;
            int nn = (t & 7) * 4;
            float4 wv = *(const float4*)&w[(size_t)(b * Ss + s) * Nn + nbase + n0 + nn];
            ws[nn + 0][s] = wv.x; ws[nn + 1][s] = wv.y;
            ws[nn + 2][s] = wv.z; ws[nn + 3][s] = wv.w;
        }
        __syncthreads();
#pragma unroll
        for (int nc = 0; nc < 32; nc++) {
            float4 a  = *(const float4*)&xs[nc][hq];
            float4 wv = *(const float4*)&ws[nc][sq];
            acc[0][0] += wv.x * a.x; acc[0][1] += wv.x * a.y; acc[0][2] += wv.x * a.z; acc[0][3] += wv.x * a.w;
            acc[1][0] += wv.y * a.x; acc[1][1] += wv.y * a.y; acc[1][2] += wv.y * a.z; acc[1][3] += wv.y * a.w;
            acc[2][0] += wv.z * a.x; acc[2][1] += wv.z * a.y; acc[2][2] += wv.z * a.z; acc[2][3] += wv.z * a.w;
            acc[3][0] += wv.w * a.x; acc[3][1] += wv.w * a.y; acc[3][2] += wv.w * a.z; acc[3][3] += wv.w * a.w;
        }
    }
#pragma unroll
    for (int i = 0; i < 4; i++) {
        float4 o = make_float4(acc[i][0], acc[i][1], acc[i][2], acc[i][3]);
        *(float4*)&g_part[(size_t)((chunk * Bq + b) * Ss + sq + i) * Hh + h0 + hq] = o;
    }
}

// ============================================================================
// k_final: deterministic split-K reduce + tanh
// ============================================================================
__global__ __launch_bounds__(256) void k_final(float* __restrict__ out) {
    int g = blockIdx.x * blockDim.x + threadIdx.x;
    float s = 0.0f;
#pragma unroll
    for (int c = 0; c < NSPLIT; c++) s += g_part[(size_t)c * (Bq * Ss * Hh) + g];
    out[g] = tanhf(s);
}

// ============================================================================
extern "C" void kernel_launch(void* const* d_in, const int* in_sizes, int n_in,
                              void* d_out, int out_size) {
    const float* x        = (const float*)d_in[0];
    const float* node_map = (const float*)d_in[1];
    const float* Wi       = (const float*)d_in[2];
    const float* bi       = (const float*)d_in[3];
    const float* Wj       = (const float*)d_in[4];
    const float* bj       = (const float*)d_in[5];
    float* out  = (float*)d_out;
    float* wout = out + (size_t)Bq * Ss * Hh;

    cudaFuncSetAttribute(k_gemm_mma, cudaFuncAttributeMaxDynamicSharedMemorySize, SM_TOT);

    k_wconv<<<(512 * Ff) / 256, 256>>>(Wi, Wj);
    k_gemm_mma<<<Mtot / 64, 512, SM_TOT>>>(x, bi, bj);
    k_weight<<<Bq * Ss, 256>>>(node_map, wout);
    k_pool<<<dim3(NSPLIT, Hh / 128, Bq), 256>>>(wout);
    k_final<<<(Bq * Ss * Hh) / 256, 256>>>(out);
}